// round 2
// baseline (speedup 1.0000x reference)
#include <cuda_runtime.h>
#include <math.h>
#include <math_constants.h>

// TopLoss: three 8M x 2 fp32 diagrams.
//   l = dgm[:,0] - dgm[:,1], non-finite -> 0
//   top1 = max(l0); t01 = 1 - top1^2; t0 = sumsq(l0) - top1^2
//   t1 = sumsq(l1); t2 = sumsq(l2); loss = t01 + t0 + t1 + t2
// Output: (loss, t01, t0, t1, t2) as 5 fp32.
//
// Pure HBM-bound single-pass reduction: 192 MiB read, ~30 us floor on B200.

#define NPAIRS   (8 * 1024 * 1024)
#define NVEC     (NPAIRS / 2)       // float4 elements per array (2 pairs each)
#define NBLK     1184               // 148 SMs * 8 CTAs
#define NTHR     256

// Per-block partials: {sumsq0, sumsq1, sumsq2, max_l0}
__device__ float4 g_partial[NBLK];

__device__ __forceinline__ float bar_len(float a, float b) {
    float l = a - b;
    return isfinite(l) ? l : 0.0f;
}

__global__ void __launch_bounds__(NTHR, 8)
toploss_pass1(const float4* __restrict__ d0,
              const float4* __restrict__ d1,
              const float4* __restrict__ d2) {
    float s0 = 0.0f, s1 = 0.0f, s2 = 0.0f;
    float m = -CUDART_INF_F;

    for (int i = blockIdx.x * NTHR + threadIdx.x; i < NVEC; i += NBLK * NTHR) {
        // issue all three loads up front (max MLP), then compute
        float4 v0 = d0[i];
        float4 v1 = d1[i];
        float4 v2 = d2[i];

        float la = bar_len(v0.x, v0.y);
        float lb = bar_len(v0.z, v0.w);
        s0 = fmaf(la, la, s0);
        s0 = fmaf(lb, lb, s0);
        m  = fmaxf(m, fmaxf(la, lb));

        la = bar_len(v1.x, v1.y);
        lb = bar_len(v1.z, v1.w);
        s1 = fmaf(la, la, s1);
        s1 = fmaf(lb, lb, s1);

        la = bar_len(v2.x, v2.y);
        lb = bar_len(v2.z, v2.w);
        s2 = fmaf(la, la, s2);
        s2 = fmaf(lb, lb, s2);
    }

    // warp reduce
    #pragma unroll
    for (int o = 16; o > 0; o >>= 1) {
        s0 += __shfl_down_sync(0xFFFFFFFFu, s0, o);
        s1 += __shfl_down_sync(0xFFFFFFFFu, s1, o);
        s2 += __shfl_down_sync(0xFFFFFFFFu, s2, o);
        m   = fmaxf(m, __shfl_down_sync(0xFFFFFFFFu, m, o));
    }

    __shared__ float sh0[NTHR / 32], sh1[NTHR / 32], sh2[NTHR / 32], shm[NTHR / 32];
    int lane = threadIdx.x & 31;
    int warp = threadIdx.x >> 5;
    if (lane == 0) { sh0[warp] = s0; sh1[warp] = s1; sh2[warp] = s2; shm[warp] = m; }
    __syncthreads();

    if (warp == 0) {
        const int nw = NTHR / 32;
        s0 = (lane < nw) ? sh0[lane] : 0.0f;
        s1 = (lane < nw) ? sh1[lane] : 0.0f;
        s2 = (lane < nw) ? sh2[lane] : 0.0f;
        m  = (lane < nw) ? shm[lane] : -CUDART_INF_F;
        #pragma unroll
        for (int o = 4; o > 0; o >>= 1) {   // nw == 8
            s0 += __shfl_down_sync(0xFFFFFFFFu, s0, o);
            s1 += __shfl_down_sync(0xFFFFFFFFu, s1, o);
            s2 += __shfl_down_sync(0xFFFFFFFFu, s2, o);
            m   = fmaxf(m, __shfl_down_sync(0xFFFFFFFFu, m, o));
        }
        if (lane == 0) g_partial[blockIdx.x] = make_float4(s0, s1, s2, m);
    }
}

__global__ void __launch_bounds__(1024)
toploss_pass2(float* __restrict__ out) {
    float s0 = 0.0f, s1 = 0.0f, s2 = 0.0f;
    float m = -CUDART_INF_F;

    for (int i = threadIdx.x; i < NBLK; i += 1024) {
        float4 p = g_partial[i];
        s0 += p.x; s1 += p.y; s2 += p.z;
        m = fmaxf(m, p.w);
    }

    #pragma unroll
    for (int o = 16; o > 0; o >>= 1) {
        s0 += __shfl_down_sync(0xFFFFFFFFu, s0, o);
        s1 += __shfl_down_sync(0xFFFFFFFFu, s1, o);
        s2 += __shfl_down_sync(0xFFFFFFFFu, s2, o);
        m   = fmaxf(m, __shfl_down_sync(0xFFFFFFFFu, m, o));
    }

    __shared__ float sh0[32], sh1[32], sh2[32], shm[32];
    int lane = threadIdx.x & 31;
    int warp = threadIdx.x >> 5;
    if (lane == 0) { sh0[warp] = s0; sh1[warp] = s1; sh2[warp] = s2; shm[warp] = m; }
    __syncthreads();

    if (warp == 0) {
        s0 = sh0[lane]; s1 = sh1[lane]; s2 = sh2[lane]; m = shm[lane];
        #pragma unroll
        for (int o = 16; o > 0; o >>= 1) {
            s0 += __shfl_down_sync(0xFFFFFFFFu, s0, o);
            s1 += __shfl_down_sync(0xFFFFFFFFu, s1, o);
            s2 += __shfl_down_sync(0xFFFFFFFFu, s2, o);
            m   = fmaxf(m, __shfl_down_sync(0xFFFFFFFFu, m, o));
        }
        if (lane == 0) {
            float m2  = m * m;
            float t01 = 1.0f - m2;
            float t0  = s0 - m2;
            out[0] = t01 + t0 + s1 + s2;  // loss
            out[1] = t01;
            out[2] = t0;
            out[3] = s1;
            out[4] = s2;
        }
    }
}

extern "C" void kernel_launch(void* const* d_in, const int* in_sizes, int n_in,
                              void* d_out, int out_size) {
    const float4* d0 = (const float4*)d_in[0];
    const float4* d1 = (const float4*)d_in[1];
    const float4* d2 = (const float4*)d_in[2];
    toploss_pass1<<<NBLK, NTHR>>>(d0, d1, d2);
    toploss_pass2<<<1, 1024>>>((float*)d_out);
}